// round 3
// baseline (speedup 1.0000x reference)
#include <cuda_runtime.h>
#include <cstdint>

#define HH 256
#define WW 256
#define NUM_CURVES 256
#define GPER 64                            /* 2 beziers * 32 samples */
#define NGAUSS (NUM_CURVES*GPER)           /* 16384 */
#define LOG2E 1.4426950408889634f
#define NSEG 8
#define SEGLEN (NGAUSS/NSEG)               /* 2048 */
#define BATCH 512
#define SUB 2                              /* BATCH / 256 */

// ---- static scratch ----
__device__ float4   d_gA[NGAUSS];     // mx, my, c0p, c1p
__device__ float4   d_gB[NGAUSS];     // c2p, log2(alpha), cr, cg
__device__ float    d_gCb[NGAUSS];    // cb
__device__ uint32_t d_gTile[NGAUSS];  // packed uchar4 tile bbox
__device__ float4   d_part[NSEG*256*256]; // per (seg,tile,pixel): rgb,T

// ---------------------------------------------------------------------------
// K1 (fused prep + bezier): 64 blocks x 256 threads.
// ---------------------------------------------------------------------------
__global__ void __launch_bounds__(256)
k_build(const float* __restrict__ ctrl,
        const float* __restrict__ fdc,
        const float* __restrict__ chol,
        const float* __restrict__ opac,
        const float* __restrict__ depth)
{
    __shared__ float  sd[NUM_CURVES];
    __shared__ int    srank[4];
    __shared__ float4 sConic[4];
    __shared__ float4 sColEx[4];
    __shared__ float  sEy[4];

    int t   = threadIdx.x;
    int grp = t >> 6;
    int li  = t & 63;
    int ci  = blockIdx.x * 4 + grp;

    sd[t] = depth[t];
    if (t < 4) srank[t] = 0;
    __syncthreads();

    {   // stable rank
        float d = sd[ci];
        int partial = 0;
        #pragma unroll
        for (int jj = 0; jj < 4; ++jj) {
            int j = li * 4 + jj;
            float dj = sd[j];
            partial += (dj < d) || (dj == d && j < ci);
        }
        partial += __shfl_xor_sync(0xffffffffu, partial, 16);
        partial += __shfl_xor_sync(0xffffffffu, partial, 8);
        partial += __shfl_xor_sync(0xffffffffu, partial, 4);
        partial += __shfl_xor_sync(0xffffffffu, partial, 2);
        partial += __shfl_xor_sync(0xffffffffu, partial, 1);
        if ((t & 31) == 0) atomicAdd(&srank[grp], partial);
    }

    if (t < 4) {
        int c = blockIdx.x * 4 + t;
        float c0 = chol[3*c+0] + 0.5f;
        float c1 = chol[3*c+1];
        float c2 = chol[3*c+2] + 0.5f;
        float s00 = c0*c0;
        float s01 = c0*c1;
        float s11 = c1*c1 + c2*c2;
        float inv = 1.0f / (s00*s11 - s01*s01);
        float A =  s11*inv;
        float B = -s01*inv;
        float C =  s00*inv;

        float al  = 1.0f / (1.0f + expf(-opac[c]));
        float l2a = log2f(al);
        float Q = fmaxf(2.0f * (19.5f + logf(al)), 0.0f);
        float ex = sqrtf(Q * s00);
        float ey = sqrtf(Q * s11);

        sConic[t] = make_float4(-0.5f*LOG2E*A, -LOG2E*B, -0.5f*LOG2E*C, l2a);
        sColEx[t] = make_float4(1.0f/(1.0f+expf(-fdc[3*c+0])),
                                1.0f/(1.0f+expf(-fdc[3*c+1])),
                                1.0f/(1.0f+expf(-fdc[3*c+2])), ex);
        sEy[t] = ey;
    }
    __syncthreads();

    int k = li >> 5;
    int s = li & 31;
    float tt = 0.007f + (float)s * (0.986f / 31.0f);
    float u  = 1.0f - tt;
    float t2 = tt*tt, t3 = t2*tt, t4 = t2*t2, t5 = t4*tt;
    float u2 = u*u,   u3 = u2*u,  u4 = u2*u2, u5 = u4*u;
    float w0 = u5, w1 = 5.0f*tt*u4, w2 = 10.0f*t2*u3;
    float w3 = 10.0f*t3*u2, w4 = 5.0f*t4*u, w5 = t5;

    const float* cb_ = ctrl + ci * 20;
    int i0 = k*5;
    int a0=i0, a1=i0+1, a2=i0+2, a3=i0+3, a4=i0+4, a5=(i0+5)%10;
    float px = w0*cb_[a0*2]   + w1*cb_[a1*2]   + w2*cb_[a2*2]
             + w3*cb_[a3*2]   + w4*cb_[a4*2]   + w5*cb_[a5*2];
    float py = w0*cb_[a0*2+1] + w1*cb_[a1*2+1] + w2*cb_[a2*2+1]
             + w3*cb_[a3*2+1] + w4*cb_[a4*2+1] + w5*cb_[a5*2+1];
    float mx = (tanhf(px)*0.5f + 0.5f) * (float)WW;
    float my = (tanhf(py)*0.5f + 0.5f) * (float)HH;

    float4 cc = sConic[grp];
    float4 ce = sColEx[grp];
    float  ey = sEy[grp];
    int slot  = srank[grp] * 64 + li;

    d_gA[slot]  = make_float4(mx, my, cc.x, cc.y);
    d_gB[slot]  = make_float4(cc.z, cc.w, ce.x, ce.y);
    d_gCb[slot] = ce.z;

    float exl = ce.w;
    int xlo = max(0,  (int)ceilf ((mx - exl - 16.0f) * 0.0625f - 1e-4f));
    int xhi = min(15, (int)floorf((mx + exl)         * 0.0625f + 1e-4f));
    int ylo = max(0,  (int)ceilf ((my - ey  - 16.0f) * 0.0625f - 1e-4f));
    int yhi = min(15, (int)floorf((my + ey)          * 0.0625f + 1e-4f));
    uint32_t packed;
    if (xlo > xhi || ylo > yhi) packed = 0x000000FFu;
    else packed = (uint32_t)xlo | ((uint32_t)xhi << 8) |
                  ((uint32_t)ylo << 16) | ((uint32_t)yhi << 24);
    d_gTile[slot] = packed;
}

// ---------------------------------------------------------------------------
// K2: depth-segmented tiled compositing.
// grid = (256 tiles, NSEG segments), 256 threads (one pixel each).
// Each block composites its 2048-gaussian depth range and emits (rgb, T).
// ---------------------------------------------------------------------------
__global__ void __launch_bounds__(256)
k_render()
{
    __shared__ float4 shA[BATCH];
    __shared__ float4 shB[BATCH];
    __shared__ float  shCb[BATCH];
    __shared__ int    warpTot[SUB][8];

    int t    = threadIdx.x;
    int wid  = t >> 5;
    int lane = t & 31;
    int tile = blockIdx.x;
    int seg  = blockIdx.y;
    int tileX = tile & 15;
    int tileY = tile >> 4;
    float px = (float)(tileX*16 + (t & 15)) + 0.5f;
    float py = (float)(tileY*16 + (t >> 4)) + 0.5f;

    float T = 1.0f, cr = 0.0f, cg = 0.0f, cb = 0.0f;
    int segBase = seg * SEGLEN;

    for (int base = segBase; base < segBase + SEGLEN; base += BATCH) {
        if (__syncthreads_and(T < 1e-4f)) break;

        unsigned bal[SUB];
        int flag[SUB];
        #pragma unroll
        for (int j = 0; j < SUB; ++j) {
            uint32_t tb = d_gTile[base + j*256 + t];
            int xlo =  tb        & 255;
            int xhi = (tb >> 8)  & 255;
            int ylo = (tb >> 16) & 255;
            int yhi =  tb >> 24;
            bool hit = (tileX >= xlo) & (tileX <= xhi) &
                       (tileY >= ylo) & (tileY <= yhi);
            flag[j] = hit;
            unsigned bb = __ballot_sync(0xffffffffu, hit);
            bal[j] = bb;
            if (lane == 0) warpTot[j][wid] = __popc(bb);
        }
        __syncthreads();

        int subBase[SUB];
        int running = 0;
        #pragma unroll
        for (int j = 0; j < SUB; ++j) {
            subBase[j] = running;
            #pragma unroll
            for (int w = 0; w < 8; ++w) running += warpTot[j][w];
        }
        int total = running;

        #pragma unroll
        for (int j = 0; j < SUB; ++j) {
            if (flag[j]) {
                int off = subBase[j] + __popc(bal[j] & ((1u << lane) - 1u));
                #pragma unroll
                for (int w = 0; w < 8; ++w)
                    if (w < wid) off += warpTot[j][w];
                int gidx = base + j*256 + t;
                shA[off]  = d_gA[gidx];
                shB[off]  = d_gB[gidx];
                shCb[off] = d_gCb[gidx];
            }
        }
        __syncthreads();

        for (int i0 = 0; i0 < total; i0 += 256) {
            int iend = min(i0 + 256, total);
            if (T >= 1e-4f) {
                for (int i = i0; i < iend; ++i) {
                    float4 A = shA[i];
                    float4 B = shB[i];
                    float dx = px - A.x;
                    float dy = py - A.y;
                    float e = B.y;
                    e = fmaf(A.z, dx*dx, e);
                    e = fmaf(A.w, dx*dy, e);
                    e = fmaf(B.x, dy*dy, e);
                    float a;
                    asm("ex2.approx.f32 %0, %1;" : "=f"(a) : "f"(e));
                    a = fminf(a, 0.999f);
                    float w = a * T;
                    cr = fmaf(w, B.z, cr);
                    cg = fmaf(w, B.w, cg);
                    cb = fmaf(w, shCb[i], cb);
                    T  = fmaf(-a, T, T);
                }
            }
            if (iend < total && __syncthreads_and(T < 1e-4f)) break;
        }
    }

    d_part[(seg*256 + tile)*256 + t] = make_float4(cr, cg, cb, T);
}

// ---------------------------------------------------------------------------
// K3: combine NSEG partials per pixel front-to-back, add background, clip.
// ---------------------------------------------------------------------------
__global__ void __launch_bounds__(256)
k_combine(const float* __restrict__ bgp, float* __restrict__ out)
{
    int t    = threadIdx.x;
    int tile = blockIdx.x;
    int tileX = tile & 15;
    int tileY = tile >> 4;

    float T = 1.0f, cr = 0.0f, cg = 0.0f, cb = 0.0f;
    #pragma unroll
    for (int s = 0; s < NSEG; ++s) {
        float4 p = d_part[(s*256 + tile)*256 + t];
        cr = fmaf(T, p.x, cr);
        cg = fmaf(T, p.y, cg);
        cb = fmaf(T, p.z, cb);
        T *= p.w;
    }

    float b0 = bgp[0], b1 = bgp[1], b2 = bgp[2];
    cr = fminf(fmaxf(fmaf(T, b0, cr), 0.0f), 1.0f);
    cg = fminf(fmaxf(fmaf(T, b1, cg), 0.0f), 1.0f);
    cb = fminf(fmaxf(fmaf(T, b2, cb), 0.0f), 1.0f);

    int o = ((tileY*16 + (t >> 4))*WW + (tileX*16 + (t & 15))) * 3;
    out[o+0] = cr;
    out[o+1] = cg;
    out[o+2] = cb;
}

// ---------------------------------------------------------------------------
extern "C" void kernel_launch(void* const* d_in, const int* in_sizes, int n_in,
                              void* d_out, int out_size)
{
    const float* ctrl  = (const float*)d_in[0];
    const float* fdc   = (const float*)d_in[1];
    const float* chol  = (const float*)d_in[2];
    const float* opac  = (const float*)d_in[3];
    const float* depth = (const float*)d_in[4];
    const float* bg    = (const float*)d_in[5];
    float* out = (float*)d_out;

    k_build<<<64, 256>>>(ctrl, fdc, chol, opac, depth);
    k_render<<<dim3(256, NSEG), 256>>>();
    k_combine<<<256, 256>>>(bg, out);
}

// round 4
// speedup vs baseline: 1.8419x; 1.8419x over previous
#include <cuda_runtime.h>
#include <cstdint>

#define HH 256
#define WW 256
#define NUM_CURVES 256
#define GPER 64                            /* 2 beziers * 32 samples */
#define NGAUSS (NUM_CURVES*GPER)           /* 16384 */
#define LOG2E 1.4426950408889634f
#define NTILE 512                          /* 16 x 32 tiles of 16x8 px */
#define MASKW (NGAUSS/32)                  /* 512 words per tile */
#define CAP 1024                           /* staged survivors per chunk */

// ---- static scratch ----
__device__ float4   d_gA[NGAUSS];            // mx, my, c0p, c1p
__device__ float4   d_gB[NGAUSS];            // c2p, log2(alpha), cr, cg
__device__ float    d_gCb[NGAUSS];           // cb
__device__ uint32_t d_mask[NTILE*MASKW];     // per-tile visibility bitmask (slot-ordered)

// ---------------------------------------------------------------------------
// K1 (fused prep + bezier + mask scatter): 64 blocks x 256 threads.
// ---------------------------------------------------------------------------
__global__ void __launch_bounds__(256)
k_build(const float* __restrict__ ctrl,
        const float* __restrict__ fdc,
        const float* __restrict__ chol,
        const float* __restrict__ opac,
        const float* __restrict__ depth)
{
    __shared__ float  sd[NUM_CURVES];
    __shared__ int    srank[4];
    __shared__ float4 sConic[4];
    __shared__ float4 sColEx[4];
    __shared__ float  sEy[4];

    int t   = threadIdx.x;
    int grp = t >> 6;
    int li  = t & 63;
    int ci  = blockIdx.x * 4 + grp;

    sd[t] = depth[t];
    if (t < 4) srank[t] = 0;
    __syncthreads();

    {   // stable rank of curve ci
        float d = sd[ci];
        int partial = 0;
        #pragma unroll
        for (int jj = 0; jj < 4; ++jj) {
            int j = li * 4 + jj;
            float dj = sd[j];
            partial += (dj < d) || (dj == d && j < ci);
        }
        partial += __shfl_xor_sync(0xffffffffu, partial, 16);
        partial += __shfl_xor_sync(0xffffffffu, partial, 8);
        partial += __shfl_xor_sync(0xffffffffu, partial, 4);
        partial += __shfl_xor_sync(0xffffffffu, partial, 2);
        partial += __shfl_xor_sync(0xffffffffu, partial, 1);
        if ((t & 31) == 0) atomicAdd(&srank[grp], partial);
    }

    if (t < 4) {
        int c = blockIdx.x * 4 + t;
        float c0 = chol[3*c+0] + 0.5f;
        float c1 = chol[3*c+1];
        float c2 = chol[3*c+2] + 0.5f;
        float s00 = c0*c0;
        float s01 = c0*c1;
        float s11 = c1*c1 + c2*c2;
        float inv = 1.0f / (s00*s11 - s01*s01);
        float A =  s11*inv;
        float B = -s01*inv;
        float C =  s00*inv;

        float al  = 1.0f / (1.0f + expf(-opac[c]));
        float l2a = log2f(al);
        float Q = fmaxf(2.0f * (19.5f + logf(al)), 0.0f);   // cutoff a >= ~3.4e-9
        float ex = sqrtf(Q * s00);
        float ey = sqrtf(Q * s11);

        sConic[t] = make_float4(-0.5f*LOG2E*A, -LOG2E*B, -0.5f*LOG2E*C, l2a);
        sColEx[t] = make_float4(1.0f/(1.0f+expf(-fdc[3*c+0])),
                                1.0f/(1.0f+expf(-fdc[3*c+1])),
                                1.0f/(1.0f+expf(-fdc[3*c+2])), ex);
        sEy[t] = ey;
    }
    __syncthreads();

    // bezier point for this thread's gaussian
    int k = li >> 5;
    int s = li & 31;
    float tt = 0.007f + (float)s * (0.986f / 31.0f);
    float u  = 1.0f - tt;
    float t2 = tt*tt, t3 = t2*tt, t4 = t2*t2, t5 = t4*tt;
    float u2 = u*u,   u3 = u2*u,  u4 = u2*u2, u5 = u4*u;
    float w0 = u5, w1 = 5.0f*tt*u4, w2 = 10.0f*t2*u3;
    float w3 = 10.0f*t3*u2, w4 = 5.0f*t4*u, w5 = t5;

    const float* cb_ = ctrl + ci * 20;
    int i0 = k*5;
    int a0=i0, a1=i0+1, a2=i0+2, a3=i0+3, a4=i0+4, a5=(i0+5)%10;
    float px = w0*cb_[a0*2]   + w1*cb_[a1*2]   + w2*cb_[a2*2]
             + w3*cb_[a3*2]   + w4*cb_[a4*2]   + w5*cb_[a5*2];
    float py = w0*cb_[a0*2+1] + w1*cb_[a1*2+1] + w2*cb_[a2*2+1]
             + w3*cb_[a3*2+1] + w4*cb_[a4*2+1] + w5*cb_[a5*2+1];
    float mx = (tanhf(px)*0.5f + 0.5f) * (float)WW;
    float my = (tanhf(py)*0.5f + 0.5f) * (float)HH;

    float4 cc = sConic[grp];
    float4 ce = sColEx[grp];
    float  ey = sEy[grp];
    int slot  = srank[grp] * 64 + li;

    d_gA[slot]  = make_float4(mx, my, cc.x, cc.y);
    d_gB[slot]  = make_float4(cc.z, cc.w, ce.x, ce.y);
    d_gCb[slot] = ce.z;

    // scatter visibility bit into 16x8-px tile masks (bit index = depth slot)
    float ex = ce.w;
    int xlo = max(0,  (int)ceilf ((mx - ex - 16.0f) * 0.0625f - 1e-4f));
    int xhi = min(15, (int)floorf((mx + ex)         * 0.0625f + 1e-4f));
    int ylo = max(0,  (int)ceilf ((my - ey - 8.0f)  * 0.125f  - 1e-4f));
    int yhi = min(31, (int)floorf((my + ey)         * 0.125f  + 1e-4f));
    if (xlo <= xhi && ylo <= yhi) {
        uint32_t bit  = 1u << (slot & 31);
        int      word = slot >> 5;
        for (int ty = ylo; ty <= yhi; ++ty)
            for (int tx = xlo; tx <= xhi; ++tx)
                atomicOr(&d_mask[(ty*16 + tx)*MASKW + word], bit);
    }
}

// ---------------------------------------------------------------------------
// K2: per-tile compositing. 512 blocks (16x8 px), 128 threads (1 px each).
// Mask -> scan -> gather -> front-to-back composite with saturation exit.
// ---------------------------------------------------------------------------
__global__ void __launch_bounds__(128)
k_render(const float* __restrict__ bgp, float* __restrict__ out)
{
    __shared__ float4 shA[CAP];
    __shared__ float4 shB[CAP];
    __shared__ float  shCb[CAP];
    __shared__ int    sW[4];

    int t    = threadIdx.x;
    int lane = t & 31;
    int wid  = t >> 5;
    int tile = blockIdx.x;
    int tx16 = tile & 15;
    int ty8  = tile >> 4;
    float px = (float)(tx16*16 + (t & 15)) + 0.5f;
    float py = (float)(ty8*8   + (t >> 4)) + 0.5f;

    // this thread owns mask words 4t..4t+3 (slots 128t..128t+127)
    uint4 mv = *(const uint4*)(d_mask + (size_t)tile*MASKW + t*4);
    int c = __popc(mv.x) + __popc(mv.y) + __popc(mv.z) + __popc(mv.w);

    // block exclusive scan of c
    int incl = c;
    #pragma unroll
    for (int d = 1; d < 32; d <<= 1) {
        int v = __shfl_up_sync(0xffffffffu, incl, d);
        if (lane >= d) incl += v;
    }
    if (lane == 31) sW[wid] = incl;
    __syncthreads();
    int wOff = 0, total = 0;
    #pragma unroll
    for (int w = 0; w < 4; ++w) {
        int v = sW[w];
        if (w < wid) wOff += v;
        total += v;
    }
    int off = wOff + incl - c;       // exclusive offset of this thread's bits

    float T = 1.0f, cr = 0.0f, cg = 0.0f, cb = 0.0f;

    for (int base = 0; base < total; base += CAP) {
        if (base > 0 && __syncthreads_and(T < 1e-4f)) break;
        int lim = min(base + CAP, total);

        // gather my survivors that fall in [base, lim)
        if (off < lim && off + c > base) {
            int o = off;
            uint32_t ms[4] = {mv.x, mv.y, mv.z, mv.w};
            #pragma unroll
            for (int w = 0; w < 4; ++w) {
                uint32_t m = ms[w];
                int sb = t*128 + w*32;
                while (m) {
                    int b = __ffs(m) - 1;
                    m &= m - 1;
                    if (o >= base && o < lim) {
                        int j = o - base;
                        int slot = sb + b;
                        shA[j]  = d_gA[slot];
                        shB[j]  = d_gB[slot];
                        shCb[j] = d_gCb[slot];
                    }
                    ++o;
                }
            }
        }
        __syncthreads();

        int n = lim - base;
        int i = 0;
        while (i < n) {
            int ie = min(i + 64, n);
            if (T >= 1e-4f) {
                for (; i < ie; ++i) {
                    float4 A = shA[i];
                    float4 B = shB[i];
                    float dx = px - A.x;
                    float dy = py - A.y;
                    float e = B.y;                       // log2(alpha)
                    e = fmaf(A.z, dx*dx, e);
                    e = fmaf(A.w, dx*dy, e);
                    e = fmaf(B.x, dy*dy, e);
                    float a;
                    asm("ex2.approx.f32 %0, %1;" : "=f"(a) : "f"(e));
                    a = fminf(a, 0.999f);
                    float w = a * T;
                    cr = fmaf(w, B.z, cr);
                    cg = fmaf(w, B.w, cg);
                    cb = fmaf(w, shCb[i], cb);
                    T  = fmaf(-a, T, T);
                }
            } else {
                i = ie;
            }
            if (__all_sync(0xffffffffu, T < 1e-4f)) i = n;   // warp-uniform skip
        }
        __syncthreads();
    }

    float b0 = bgp[0], b1 = bgp[1], b2 = bgp[2];
    cr = fminf(fmaxf(fmaf(T, b0, cr), 0.0f), 1.0f);
    cg = fminf(fmaxf(fmaf(T, b1, cg), 0.0f), 1.0f);
    cb = fminf(fmaxf(fmaf(T, b2, cb), 0.0f), 1.0f);

    int o = ((ty8*8 + (t >> 4))*WW + (tx16*16 + (t & 15))) * 3;
    out[o+0] = cr;
    out[o+1] = cg;
    out[o+2] = cb;
}

// ---------------------------------------------------------------------------
extern "C" void kernel_launch(void* const* d_in, const int* in_sizes, int n_in,
                              void* d_out, int out_size)
{
    const float* ctrl  = (const float*)d_in[0];
    const float* fdc   = (const float*)d_in[1];
    const float* chol  = (const float*)d_in[2];
    const float* opac  = (const float*)d_in[3];
    const float* depth = (const float*)d_in[4];
    const float* bg    = (const float*)d_in[5];
    float* out = (float*)d_out;

    void* maskPtr = nullptr;
    cudaGetSymbolAddress(&maskPtr, d_mask);
    cudaMemsetAsync(maskPtr, 0, NTILE*MASKW*sizeof(uint32_t), 0);

    k_build<<<64, 256>>>(ctrl, fdc, chol, opac, depth);
    k_render<<<NTILE, 128>>>(bg, out);
}

// round 5
// speedup vs baseline: 1.8439x; 1.0011x over previous
#include <cuda_runtime.h>
#include <cstdint>

#define HH 256
#define WW 256
#define NUM_CURVES 256
#define GPER 64                            /* 2 beziers * 32 samples */
#define NGAUSS (NUM_CURVES*GPER)           /* 16384 */
#define LOG2E 1.4426950408889634f
#define NTILE 1024                         /* 32 x 32 tiles of 8x8 px */
#define MASKW (NGAUSS/32)                  /* 512 words per tile */
#define CAP 512                            /* staged survivors per chunk */

// ---- static scratch ----
__device__ float4   d_gA[NGAUSS];            // mx, my, c0p, c1p
__device__ float4   d_gB[NGAUSS];            // c2p, log2(alpha), cr, cg
__device__ float    d_gCb[NGAUSS];           // cb
__device__ uint32_t d_mask[NTILE*MASKW];     // per-tile visibility bitmask (slot-ordered)

// ---------------------------------------------------------------------------
// K1 (fused prep + bezier + mask scatter): 64 blocks x 256 threads.
// ---------------------------------------------------------------------------
__global__ void __launch_bounds__(256)
k_build(const float* __restrict__ ctrl,
        const float* __restrict__ fdc,
        const float* __restrict__ chol,
        const float* __restrict__ opac,
        const float* __restrict__ depth)
{
    __shared__ float  sd[NUM_CURVES];
    __shared__ int    srank[4];
    __shared__ float4 sConic[4];
    __shared__ float4 sColEx[4];
    __shared__ float  sEy[4];

    int t   = threadIdx.x;
    int grp = t >> 6;
    int li  = t & 63;
    int ci  = blockIdx.x * 4 + grp;

    sd[t] = depth[t];
    if (t < 4) srank[t] = 0;
    __syncthreads();

    {   // stable rank of curve ci
        float d = sd[ci];
        int partial = 0;
        #pragma unroll
        for (int jj = 0; jj < 4; ++jj) {
            int j = li * 4 + jj;
            float dj = sd[j];
            partial += (dj < d) || (dj == d && j < ci);
        }
        partial += __shfl_xor_sync(0xffffffffu, partial, 16);
        partial += __shfl_xor_sync(0xffffffffu, partial, 8);
        partial += __shfl_xor_sync(0xffffffffu, partial, 4);
        partial += __shfl_xor_sync(0xffffffffu, partial, 2);
        partial += __shfl_xor_sync(0xffffffffu, partial, 1);
        if ((t & 31) == 0) atomicAdd(&srank[grp], partial);
    }

    if (t < 4) {
        int c = blockIdx.x * 4 + t;
        float c0 = chol[3*c+0] + 0.5f;
        float c1 = chol[3*c+1];
        float c2 = chol[3*c+2] + 0.5f;
        float s00 = c0*c0;
        float s01 = c0*c1;
        float s11 = c1*c1 + c2*c2;
        float inv = 1.0f / (s00*s11 - s01*s01);
        float A =  s11*inv;
        float B = -s01*inv;
        float C =  s00*inv;

        float al  = 1.0f / (1.0f + expf(-opac[c]));
        float l2a = log2f(al);
        float Q = fmaxf(2.0f * (19.5f + logf(al)), 0.0f);   // cutoff a >= ~3.4e-9
        float ex = sqrtf(Q * s00);
        float ey = sqrtf(Q * s11);

        sConic[t] = make_float4(-0.5f*LOG2E*A, -LOG2E*B, -0.5f*LOG2E*C, l2a);
        sColEx[t] = make_float4(1.0f/(1.0f+expf(-fdc[3*c+0])),
                                1.0f/(1.0f+expf(-fdc[3*c+1])),
                                1.0f/(1.0f+expf(-fdc[3*c+2])), ex);
        sEy[t] = ey;
    }
    __syncthreads();

    // bezier point for this thread's gaussian
    int k = li >> 5;
    int s = li & 31;
    float tt = 0.007f + (float)s * (0.986f / 31.0f);
    float u  = 1.0f - tt;
    float t2 = tt*tt, t3 = t2*tt, t4 = t2*t2, t5 = t4*tt;
    float u2 = u*u,   u3 = u2*u,  u4 = u2*u2, u5 = u4*u;
    float w0 = u5, w1 = 5.0f*tt*u4, w2 = 10.0f*t2*u3;
    float w3 = 10.0f*t3*u2, w4 = 5.0f*t4*u, w5 = t5;

    const float* cb_ = ctrl + ci * 20;
    int i0 = k*5;
    int a0=i0, a1=i0+1, a2=i0+2, a3=i0+3, a4=i0+4, a5=(i0+5)%10;
    float px = w0*cb_[a0*2]   + w1*cb_[a1*2]   + w2*cb_[a2*2]
             + w3*cb_[a3*2]   + w4*cb_[a4*2]   + w5*cb_[a5*2];
    float py = w0*cb_[a0*2+1] + w1*cb_[a1*2+1] + w2*cb_[a2*2+1]
             + w3*cb_[a3*2+1] + w4*cb_[a4*2+1] + w5*cb_[a5*2+1];
    float mx = (tanhf(px)*0.5f + 0.5f) * (float)WW;
    float my = (tanhf(py)*0.5f + 0.5f) * (float)HH;

    float4 cc = sConic[grp];
    float4 ce = sColEx[grp];
    float  ey = sEy[grp];
    int slot  = srank[grp] * 64 + li;

    d_gA[slot]  = make_float4(mx, my, cc.x, cc.y);
    d_gB[slot]  = make_float4(cc.z, cc.w, ce.x, ce.y);
    d_gCb[slot] = ce.z;

    // scatter visibility bit into 8x8-px tile masks (bit index = depth slot)
    float ex = ce.w;
    int xlo = max(0,  (int)ceilf ((mx - ex - 8.0f) * 0.125f - 1e-4f));
    int xhi = min(31, (int)floorf((mx + ex)        * 0.125f + 1e-4f));
    int ylo = max(0,  (int)ceilf ((my - ey - 8.0f) * 0.125f - 1e-4f));
    int yhi = min(31, (int)floorf((my + ey)        * 0.125f + 1e-4f));
    if (xlo <= xhi && ylo <= yhi) {
        uint32_t bit  = 1u << (slot & 31);
        int      word = slot >> 5;
        for (int ty = ylo; ty <= yhi; ++ty)
            for (int tx = xlo; tx <= xhi; ++tx)
                atomicOr(&d_mask[(ty*32 + tx)*MASKW + word], bit);
    }
}

// ---------------------------------------------------------------------------
// K2: per-tile compositing. 1024 blocks (8x8 px), 64 threads (1 px each).
// Mask -> scan -> gather -> front-to-back composite with saturation exit.
// ---------------------------------------------------------------------------
__global__ void __launch_bounds__(64)
k_render(const float* __restrict__ bgp, float* __restrict__ out)
{
    __shared__ float4 shA[CAP];
    __shared__ float4 shB[CAP];
    __shared__ float  shCb[CAP];
    __shared__ int    sW[2];

    int t    = threadIdx.x;
    int lane = t & 31;
    int wid  = t >> 5;
    int tile = blockIdx.x;
    int tx8  = tile & 31;
    int ty8  = tile >> 5;
    float px = (float)(tx8*8 + (t & 7)) + 0.5f;
    float py = (float)(ty8*8 + (t >> 3)) + 0.5f;

    // this thread owns mask words 8t..8t+7 (slots 256t..256t+255)
    const uint32_t* mw = d_mask + (size_t)tile*MASKW + t*8;
    uint4 m0 = *(const uint4*)(mw);
    uint4 m1 = *(const uint4*)(mw + 4);
    int c = __popc(m0.x) + __popc(m0.y) + __popc(m0.z) + __popc(m0.w)
          + __popc(m1.x) + __popc(m1.y) + __popc(m1.z) + __popc(m1.w);

    // block exclusive scan of c (2 warps)
    int incl = c;
    #pragma unroll
    for (int d = 1; d < 32; d <<= 1) {
        int v = __shfl_up_sync(0xffffffffu, incl, d);
        if (lane >= d) incl += v;
    }
    if (lane == 31) sW[wid] = incl;
    __syncthreads();
    int w0s = sW[0], w1s = sW[1];
    int total = w0s + w1s;
    int off = (wid ? w0s : 0) + incl - c;   // exclusive offset of this thread's bits

    float T = 1.0f, cr = 0.0f, cg = 0.0f, cb = 0.0f;

    for (int base = 0; base < total; base += CAP) {
        if (base > 0 && __syncthreads_and(T < 1e-4f)) break;
        int lim = min(base + CAP, total);

        // gather my survivors that fall in [base, lim)
        if (off < lim && off + c > base) {
            int o = off;
            uint32_t ms[8] = {m0.x, m0.y, m0.z, m0.w, m1.x, m1.y, m1.z, m1.w};
            #pragma unroll
            for (int w = 0; w < 8; ++w) {
                uint32_t m = ms[w];
                int sb = t*256 + w*32;
                while (m) {
                    int b = __ffs(m) - 1;
                    m &= m - 1;
                    if (o >= base && o < lim) {
                        int j = o - base;
                        int slot = sb + b;
                        shA[j]  = d_gA[slot];
                        shB[j]  = d_gB[slot];
                        shCb[j] = d_gCb[slot];
                    }
                    ++o;
                }
            }
        }
        __syncthreads();

        int n = lim - base;
        int i = 0;
        while (i < n) {
            int ie = min(i + 64, n);
            if (T >= 1e-4f) {
                for (; i < ie; ++i) {
                    float4 A = shA[i];
                    float4 B = shB[i];
                    float dx = px - A.x;
                    float dy = py - A.y;
                    float e = B.y;                       // log2(alpha)
                    e = fmaf(A.z, dx*dx, e);
                    e = fmaf(A.w, dx*dy, e);
                    e = fmaf(B.x, dy*dy, e);
                    float a;
                    asm("ex2.approx.f32 %0, %1;" : "=f"(a) : "f"(e));
                    // no clamp: alpha = sigmoid(1) = 0.731 < 0.999 provably
                    float w = a * T;
                    cr = fmaf(w, B.z, cr);
                    cg = fmaf(w, B.w, cg);
                    cb = fmaf(w, shCb[i], cb);
                    T  = fmaf(-a, T, T);
                }
            } else {
                i = ie;
            }
            if (__all_sync(0xffffffffu, T < 1e-4f)) i = n;   // warp-uniform skip
        }
        __syncthreads();
    }

    float b0 = bgp[0], b1 = bgp[1], b2 = bgp[2];
    cr = fminf(fmaxf(fmaf(T, b0, cr), 0.0f), 1.0f);
    cg = fminf(fmaxf(fmaf(T, b1, cg), 0.0f), 1.0f);
    cb = fminf(fmaxf(fmaf(T, b2, cb), 0.0f), 1.0f);

    int o = ((ty8*8 + (t >> 3))*WW + (tx8*8 + (t & 7))) * 3;
    out[o+0] = cr;
    out[o+1] = cg;
    out[o+2] = cb;
}

// ---------------------------------------------------------------------------
extern "C" void kernel_launch(void* const* d_in, const int* in_sizes, int n_in,
                              void* d_out, int out_size)
{
    const float* ctrl  = (const float*)d_in[0];
    const float* fdc   = (const float*)d_in[1];
    const float* chol  = (const float*)d_in[2];
    const float* opac  = (const float*)d_in[3];
    const float* depth = (const float*)d_in[4];
    const float* bg    = (const float*)d_in[5];
    float* out = (float*)d_out;

    void* maskPtr = nullptr;
    cudaGetSymbolAddress(&maskPtr, d_mask);
    cudaMemsetAsync(maskPtr, 0, NTILE*MASKW*sizeof(uint32_t), 0);

    k_build<<<64, 256>>>(ctrl, fdc, chol, opac, depth);
    k_render<<<NTILE, 64>>>(bg, out);
}